// round 10
// baseline (speedup 1.0000x reference)
#include <cuda_runtime.h>
#include <cuda_bf16.h>

// Fused single-kernel deterministic reduction: out = sum(x) * a * b
// x: 8192*8192 fp32 (d_in[0]), a,b: scalar fp32 (d_in[1], d_in[2]).
//
// Full-capacity single wave: 1216 CTAs = 152 SMs x 8 (100% occupancy),
// with an exact uneven-but-uniform split of the 2^24 float4:
//   CTAs    0..1023: 13 groups -> 52 float4/thread (13,631,488 total)
//   CTAs 1024..1215: 16 groups -> 64 float4/thread ( 3,145,728 total)
// Each group = 4 independent LDG.128 off one base register
// (+0/+4KB/+8KB/+12KB immediate offsets) -> guaranteed 4-deep memory
// pipeline (the R7-winning codegen), single code path via runtime group
// count. No bounds checks anywhere in the mainloop.

#define R_BLOCKS  1216
#define R_THREADS 256
#define R_SPLIT   1024u          // CTAs below this do 13 groups, rest 16
#define R_G_LIGHT 13
#define R_G_HEAVY 16
#define R_LIGHT_CHUNK 13312u     // 256 * 52 float4 per light CTA
#define R_HEAVY_BASE  13631488u  // 1024 * 13312
#define R_HEAVY_CHUNK 16384u     // 256 * 64 float4 per heavy CTA

__device__ float g_partials[R_BLOCKS];
__device__ unsigned int g_count = 0;   // self-resetting: graph-replay safe

__device__ __forceinline__ float block_reduce(float s)
{
    #pragma unroll
    for (int o = 16; o > 0; o >>= 1)
        s += __shfl_xor_sync(0xffffffffu, s, o);

    __shared__ float sh[R_THREADS / 32];
    int lane = threadIdx.x & 31;
    int warp = threadIdx.x >> 5;
    if (lane == 0) sh[warp] = s;
    __syncthreads();

    if (warp == 0) {
        s = (lane < (R_THREADS / 32)) ? sh[lane] : 0.f;
        #pragma unroll
        for (int o = 16; o > 0; o >>= 1)
            s += __shfl_xor_sync(0xffffffffu, s, o);
    }
    return s;  // valid in warp 0 lane 0
}

__global__ void __launch_bounds__(R_THREADS) reduce_fused(
    const float4* __restrict__ x4,
    const float* __restrict__ a, const float* __restrict__ b,
    float* __restrict__ out)
{
    const unsigned bid = blockIdx.x;

    // Contiguous chunk base + per-CTA uniform group count.
    const float4* p;
    int ngroups;
    if (bid < R_SPLIT) {
        p = x4 + bid * R_LIGHT_CHUNK + threadIdx.x;
        ngroups = R_G_LIGHT;
    } else {
        p = x4 + R_HEAVY_BASE + (bid - R_SPLIT) * R_HEAVY_CHUNK + threadIdx.x;
        ngroups = R_G_HEAVY;
    }

    float s0 = 0.f, s1 = 0.f, s2 = 0.f, s3 = 0.f;

    #pragma unroll 1
    for (int g = 0; g < ngroups; g++) {
        // 4 independent LDG.128 off one base register, issued before any
        // consumer -> 4-deep memory pipeline (proven fastest codegen).
        float4 v0 = p[0];
        float4 v1 = p[256];
        float4 v2 = p[512];
        float4 v3 = p[768];
        s0 += (v0.x + v1.x) + (v2.x + v3.x);
        s1 += (v0.y + v1.y) + (v2.y + v3.y);
        s2 += (v0.z + v1.z) + (v2.z + v3.z);
        s3 += (v0.w + v1.w) + (v2.w + v3.w);
        p += 1024;
    }

    float s = block_reduce((s0 + s1) + (s2 + s3));

    __shared__ bool is_last;
    if (threadIdx.x == 0) {
        g_partials[bid] = s;
        __threadfence();
        unsigned int prev = atomicAdd(&g_count, 1u);
        is_last = (prev == (unsigned)(R_BLOCKS - 1));
    }
    __syncthreads();

    if (is_last) {
        // Deterministic final fold: fixed per-thread strided order.
        float t = 0.f;
        for (int i = threadIdx.x; i < R_BLOCKS; i += R_THREADS)
            t += g_partials[i];
        t = block_reduce(t);
        if (threadIdx.x == 0) {
            out[0] = t * a[0] * b[0];
            g_count = 0;   // reset for next graph replay
        }
    }
}

extern "C" void kernel_launch(void* const* d_in, const int* in_sizes, int n_in,
                              void* d_out, int out_size)
{
    const float4* x4 = (const float4*)d_in[0];
    const float* a   = (const float*)d_in[1];
    const float* b   = (const float*)d_in[2];
    float* out       = (float*)d_out;

    reduce_fused<<<R_BLOCKS, R_THREADS>>>(x4, a, b, out);
}

// round 11
// speedup vs baseline: 1.0553x; 1.0553x over previous
#include <cuda_runtime.h>
#include <cuda_bf16.h>

// Fused single-kernel deterministic reduction: out = sum(x) * a * b
// x: 8192*8192 fp32 (d_in[0]), a,b: scalar fp32 (d_in[1], d_in[2]).
//
// R7-winning geometry (1024 CTAs x 256 thr, block-contiguous 256KB chunks,
// uniform trip count) upgraded to 256-bit loads (ld.global.v8.f32, sm_100+):
// half the LDG issue count and half the L1tex wavefront-queue entries for
// the same bytes in flight (2 x 32B vs 4 x 16B per thread-group).
//
// Per block: 65536 floats contiguous. Per thread: 256 floats = 32 v8-loads,
// as 16 groups of 2 independent LDG.256. ~30 regs -> 8 CTAs/SM.

#define R_BLOCKS  1024
#define R_THREADS 256
#define R_GROUPS  16
#define R_CHUNK_F 65536u   // floats per block

__device__ float g_partials[R_BLOCKS];
__device__ unsigned int g_count = 0;   // self-resetting: graph-replay safe

__device__ __forceinline__ float block_reduce(float s)
{
    #pragma unroll
    for (int o = 16; o > 0; o >>= 1)
        s += __shfl_xor_sync(0xffffffffu, s, o);

    __shared__ float sh[R_THREADS / 32];
    int lane = threadIdx.x & 31;
    int warp = threadIdx.x >> 5;
    if (lane == 0) sh[warp] = s;
    __syncthreads();

    if (warp == 0) {
        s = (lane < (R_THREADS / 32)) ? sh[lane] : 0.f;
        #pragma unroll
        for (int o = 16; o > 0; o >>= 1)
            s += __shfl_xor_sync(0xffffffffu, s, o);
    }
    return s;  // valid in warp 0 lane 0
}

// 256-bit global load (sm_100a/sm_103a): 8 consecutive floats, 32B-aligned.
__device__ __forceinline__ void ldg256(const float* __restrict__ p, float v[8])
{
    asm volatile("ld.global.v8.f32 {%0,%1,%2,%3,%4,%5,%6,%7}, [%8];"
        : "=f"(v[0]), "=f"(v[1]), "=f"(v[2]), "=f"(v[3]),
          "=f"(v[4]), "=f"(v[5]), "=f"(v[6]), "=f"(v[7])
        : "l"(p));
}

__global__ void __launch_bounds__(R_THREADS) reduce_fused(
    const float* __restrict__ x,
    const float* __restrict__ a, const float* __restrict__ b,
    float* __restrict__ out)
{
    // Thread's base inside this block's contiguous 65536-float chunk.
    // Lane stride 8 floats (32B): a warp's LDG.256 covers 1024B contiguous.
    const float* q = x + (unsigned)blockIdx.x * R_CHUNK_F + threadIdx.x * 8u;

    float acc[8];
    #pragma unroll
    for (int i = 0; i < 8; i++) acc[i] = 0.f;

    #pragma unroll 1
    for (int g = 0; g < R_GROUPS; g++) {
        // Two independent LDG.256 issued back-to-back (+0 / +8KB),
        // consumed only after both are in flight.
        float v0[8], v1[8];
        ldg256(q,        v0);
        ldg256(q + 2048, v1);
        #pragma unroll
        for (int i = 0; i < 8; i++)
            acc[i] += v0[i] + v1[i];
        q += 4096;
    }

    float s = ((acc[0] + acc[1]) + (acc[2] + acc[3]))
            + ((acc[4] + acc[5]) + (acc[6] + acc[7]));
    s = block_reduce(s);

    __shared__ bool is_last;
    if (threadIdx.x == 0) {
        g_partials[blockIdx.x] = s;
        __threadfence();
        unsigned int prev = atomicAdd(&g_count, 1u);
        is_last = (prev == (unsigned)(R_BLOCKS - 1));
    }
    __syncthreads();

    if (is_last) {
        // Deterministic final fold: fixed per-thread strided order.
        float t = 0.f;
        #pragma unroll
        for (int i = 0; i < R_BLOCKS / R_THREADS; i++)
            t += g_partials[threadIdx.x + i * R_THREADS];
        t = block_reduce(t);
        if (threadIdx.x == 0) {
            out[0] = t * a[0] * b[0];
            g_count = 0;   // reset for next graph replay
        }
    }
}

extern "C" void kernel_launch(void* const* d_in, const int* in_sizes, int n_in,
                              void* d_out, int out_size)
{
    const float* x = (const float*)d_in[0];
    const float* a = (const float*)d_in[1];
    const float* b = (const float*)d_in[2];
    float* out     = (float*)d_out;

    reduce_fused<<<R_BLOCKS, R_THREADS>>>(x, a, b, out);
}